// round 6
// baseline (speedup 1.0000x reference)
#include <cuda_runtime.h>
#include <cstdint>
#include <math.h>

#define BB 16
#define L_TOTAL 327
#define S_DIM 256
#define Z_DIM 64
#define S_IN 21
#define PE_DIM 64
#define MAXPOS 104
#define TB 4                      // batches per block
#define NGRP (BB / TB)            // 4 b-groups

__constant__ int c_starts[7] = {1, 25, 41, 89, 193, 209, 313};
__constant__ int c_lens[7]   = {24, 16, 48, 104, 16, 104, 14};

// Precomputed scratch
__device__ float g_pe[MAXPOS * S_DIM];      // PE projection table
__device__ float g_table[32 * 64];          // z vocabulary (32 rows x 64)

__device__ __forceinline__ int reg_of(int i) {
    if (i == 0)  return 0;
    if (i < 25)  return 1;
    if (i < 41)  return 2;
    if (i < 89)  return 3;
    if (i < 193) return 4;
    if (i < 209) return 5;
    if (i < 313) return 6;
    return 7;
}

__device__ __forceinline__ int pair_id(int i, int j) {
    int ri = reg_of(i), rj = reg_of(j);
    int p = 0;
    if (i == 0 || j == 0) p = 1;
    if (i == 0 && j == 0) p = 0;
    bool cb = (ri == 1) && (rj == 1);
    int d = (i > j) ? (i - j) : (j - i);
    if (cb && d == 1) p = 2;
    if (cb && i != j && d != 1) p = 3;
    if ((ri == 1 && rj >= 2) || (ri >= 2 && rj == 1)) p = 4;
    if (ri >= 2 && ri == rj) p = 5 + (ri - 2);
    if (ri >= 2 && rj >= 2 && ri != rj) {
        int a = (ri < rj ? ri : rj) - 2;
        int b = (ri > rj ? ri : rj) - 2;
        p = 11 + a * (11 - a) / 2 + (b - a - 1);
    }
    return (p < 31) ? p : 31;
}

// ---------------- setup kernel: blocks [0,104) = g_pe rows, block 104 = g_table ------
__global__ void __launch_bounds__(256)
setup_kernel(const float* __restrict__ pos_W, const float* __restrict__ pos_b,
             const float* __restrict__ pair1_W, const float* __restrict__ pair1_b,
             const float* __restrict__ pair2_W, const float* __restrict__ pair2_b)
{
    const int bid = blockIdx.x;
    const int c   = threadIdx.x;

    if (bid < MAXPOS) {
        __shared__ float4 perow4[PE_DIM / 4];
        const int pos = bid;
        if (c < PE_DIM) {
            float inv = exp2f(-(float)c * (13.287712379549449f / 64.0f));
            float ang = (float)pos * inv;
            ((float*)perow4)[c] = (c & 1) ? cosf(ang) : sinf(ang);
        }
        __syncthreads();
        float pe = pos_b[c];
        const float4* pw = (const float4*)(pos_W + c * PE_DIM);
        float pe1 = 0.f;
        #pragma unroll
        for (int q = 0; q < 16; q += 2) {
            float4 w0 = pw[q],   p0 = perow4[q];
            float4 w1 = pw[q+1], p1 = perow4[q+1];
            pe  = fmaf(p0.x, w0.x, pe);  pe  = fmaf(p0.y, w0.y, pe);
            pe  = fmaf(p0.z, w0.z, pe);  pe  = fmaf(p0.w, w0.w, pe);
            pe1 = fmaf(p1.x, w1.x, pe1); pe1 = fmaf(p1.y, w1.y, pe1);
            pe1 = fmaf(p1.z, w1.z, pe1); pe1 = fmaf(p1.w, w1.w, pe1);
        }
        g_pe[pos * S_DIM + c] = pe + pe1;
    } else {
        for (int idx = c; idx < 32 * 64; idx += 256) {
            int p  = idx >> 6;
            int cc = idx & 63;
            float v;
            if (cc < 32) v = pair1_W[cc * 8 + (p >> 2)] + pair1_b[cc];
            else { int c2 = cc - 32; v = pair2_W[c2 * 4 + (p & 3)] + pair2_b[c2]; }
            g_table[idx] = v;
        }
    }
}

// ---------------- fused kernel: one block per (i, b-group of 4) --------------------
__global__ void __launch_bounds__(256)
fused_kernel(const float* __restrict__ s0, const float* __restrict__ s1,
             const float* __restrict__ s2, const float* __restrict__ s3,
             const float* __restrict__ s4, const float* __restrict__ s5,
             const float* __restrict__ s6,
             const float* __restrict__ seq_W, const float* __restrict__ seq_b,
             const float* __restrict__ collapse_token,
             const float* __restrict__ collapse_weight,
             const float* __restrict__ region_w,
             float* __restrict__ sout, float* __restrict__ zout)
{
    __shared__ float4 table[32 * 16];
    __shared__ unsigned char prow[L_TOTAL + 1];
    __shared__ float srow[TB][S_IN];

    const int bid = blockIdx.x;                 // grp * L_TOTAL + i
    const int i   = bid % L_TOTAL;
    const int grp = bid / L_TOTAL;              // 0..3
    const int b0  = grp * TB;
    const int c   = threadIdx.x;

    // Prologue (amortized over TB rows)
    {
        const float4* gt = (const float4*)g_table;
        table[c]       = gt[c];
        table[c + 256] = gt[c + 256];
    }
    for (int j = c; j < L_TOTAL; j += 256)
        prow[j] = (unsigned char)pair_id(i, j);

    int k = 0, pos = 0;
    const float* seqp = s0;
    if (i > 0) {
        k   = reg_of(i) - 1;
        pos = i - c_starts[k];
        switch (k) {
            case 0: seqp = s0; break;
            case 1: seqp = s1; break;
            case 2: seqp = s2; break;
            case 3: seqp = s3; break;
            case 4: seqp = s4; break;
            case 5: seqp = s5; break;
            default: seqp = s6; break;
        }
        // load all TB seq rows for this token position at once (84 threads)
        if (c < TB * S_IN) {
            int g = c / S_IN, d = c - g * S_IN;
            srow[g][d] = seqp[((size_t)(b0 + g) * c_lens[k] + pos) * S_IN + d];
        }
    }
    __syncthreads();

    // ---- s rows for the TB tokens ----
    if (i == 0) {
        float ct = collapse_weight[0] * collapse_token[c];
        #pragma unroll
        for (int g = 0; g < TB; g++)
            sout[((size_t)(b0 + g) * L_TOTAL) * S_DIM + c] = ct;
    } else {
        // per-thread register weights for channel c
        float sw[S_IN];
        const float* w = seq_W + c * S_IN;
        #pragma unroll
        for (int d = 0; d < S_IN; d++) sw[d] = w[d];
        const float sb  = seq_b[c];
        const float pe  = g_pe[pos * S_DIM + c];
        const float rw0 = region_w[2 * k], rw1 = region_w[2 * k + 1];
        #pragma unroll
        for (int g = 0; g < TB; g++) {
            float se = sb;
            #pragma unroll
            for (int d = 0; d < S_IN; d++) se = fmaf(srow[g][d], sw[d], se);
            sout[((size_t)(b0 + g) * L_TOTAL + i) * S_DIM + c] = rw0 * se + rw1 * pe;
        }
    }

    // ---- z rows: one table LDS feeds TB streaming stores ----
    const size_t rowq = (size_t)L_TOTAL * (Z_DIM / 4);           // 5232 float4 per row
    float4* zr0 = (float4*)zout + ((size_t)b0 * L_TOTAL + i) * rowq;
    const int total = L_TOTAL * (Z_DIM / 4);
    for (int v = c; v < total; v += 256) {
        int j = v >> 4;
        float4 val = table[((int)prow[j] << 4) + (v & 15)];
        float4* p = zr0 + v;
        #pragma unroll
        for (int g = 0; g < TB; g++) {
            __stcs(p, val);
            p += (size_t)L_TOTAL * rowq;                         // next batch, same i
        }
    }
}

extern "C" void kernel_launch(void* const* d_in, const int* in_sizes, int n_in,
                              void* d_out, int out_size)
{
    (void)in_sizes; (void)n_in; (void)out_size;
    // 0..6 region seqs, 7 seq_W, 8 seq_b, 9 pos_W, 10 pos_b, 11 pair1_W, 12 pair1_b,
    // 13 pair2_W, 14 pair2_b, 15 collapse_token, 16 collapse_weight, 17 region_w,
    // 18..24 masks (unused)
    float* out  = (float*)d_out;
    float* zout = out + (size_t)BB * L_TOTAL * S_DIM;   // z follows s

    setup_kernel<<<MAXPOS + 1, 256>>>(
        (const float*)d_in[9],  (const float*)d_in[10],
        (const float*)d_in[11], (const float*)d_in[12],
        (const float*)d_in[13], (const float*)d_in[14]);

    fused_kernel<<<NGRP * L_TOTAL, 256>>>(
        (const float*)d_in[0], (const float*)d_in[1], (const float*)d_in[2],
        (const float*)d_in[3], (const float*)d_in[4], (const float*)d_in[5],
        (const float*)d_in[6],
        (const float*)d_in[7], (const float*)d_in[8],
        (const float*)d_in[15], (const float*)d_in[16],
        (const float*)d_in[17],
        out, zout);
}

// round 7
// speedup vs baseline: 1.4436x; 1.4436x over previous
#include <cuda_runtime.h>
#include <cstdint>
#include <math.h>

#define BB 16
#define L_TOTAL 327
#define PROW_PITCH 328
#define S_DIM 256
#define Z_DIM 64
#define S_IN 21
#define PE_DIM 64
#define MAXPOS 104
#define PROW_PER_BLK 8
#define PROW_BLKS ((L_TOTAL + PROW_PER_BLK - 1) / PROW_PER_BLK)   // 41

__constant__ int c_starts[7] = {1, 25, 41, 89, 193, 209, 313};
__constant__ int c_lens[7]   = {24, 16, 48, 104, 16, 104, 14};

// Precomputed scratch
__device__ float g_pe[MAXPOS * S_DIM];                    // PE projection table
__device__ float g_table[32 * 64];                        // z vocabulary
__device__ float g_seqWT[S_IN * S_DIM];                   // seq_W transposed [d][c]
__device__ unsigned char g_prow[L_TOTAL * PROW_PITCH];    // pair-id matrix

__device__ __forceinline__ int reg_of(int i) {
    if (i == 0)  return 0;
    if (i < 25)  return 1;
    if (i < 41)  return 2;
    if (i < 89)  return 3;
    if (i < 193) return 4;
    if (i < 209) return 5;
    if (i < 313) return 6;
    return 7;
}

__device__ __forceinline__ int pair_id(int i, int j) {
    int ri = reg_of(i), rj = reg_of(j);
    int p = 0;
    if (i == 0 || j == 0) p = 1;
    if (i == 0 && j == 0) p = 0;
    bool cb = (ri == 1) && (rj == 1);
    int d = (i > j) ? (i - j) : (j - i);
    if (cb && d == 1) p = 2;
    if (cb && i != j && d != 1) p = 3;
    if ((ri == 1 && rj >= 2) || (ri >= 2 && rj == 1)) p = 4;
    if (ri >= 2 && ri == rj) p = 5 + (ri - 2);
    if (ri >= 2 && rj >= 2 && ri != rj) {
        int a = (ri < rj ? ri : rj) - 2;
        int b = (ri > rj ? ri : rj) - 2;
        p = 11 + a * (11 - a) / 2 + (b - a - 1);
    }
    return (p < 31) ? p : 31;
}

// ---------------- setup kernel ----------------
// blocks [0,104):            g_pe rows
// block  104:                g_table + seq_W transpose
// blocks [105, 105+41):      g_prow, 8 rows each
__global__ void __launch_bounds__(256)
setup_kernel(const float* __restrict__ pos_W, const float* __restrict__ pos_b,
             const float* __restrict__ pair1_W, const float* __restrict__ pair1_b,
             const float* __restrict__ pair2_W, const float* __restrict__ pair2_b,
             const float* __restrict__ seq_W)
{
    const int bid = blockIdx.x;
    const int c   = threadIdx.x;

    if (bid < MAXPOS) {
        __shared__ float4 perow4[PE_DIM / 4];
        const int pos = bid;
        if (c < PE_DIM) {
            float inv = exp2f(-(float)c * (13.287712379549449f / 64.0f));
            float ang = (float)pos * inv;
            ((float*)perow4)[c] = (c & 1) ? cosf(ang) : sinf(ang);
        }
        __syncthreads();
        float pe = pos_b[c];
        const float4* pw = (const float4*)(pos_W + c * PE_DIM);
        float pe1 = 0.f;
        #pragma unroll
        for (int q = 0; q < 16; q += 2) {
            float4 w0 = pw[q],   p0 = perow4[q];
            float4 w1 = pw[q+1], p1 = perow4[q+1];
            pe  = fmaf(p0.x, w0.x, pe);  pe  = fmaf(p0.y, w0.y, pe);
            pe  = fmaf(p0.z, w0.z, pe);  pe  = fmaf(p0.w, w0.w, pe);
            pe1 = fmaf(p1.x, w1.x, pe1); pe1 = fmaf(p1.y, w1.y, pe1);
            pe1 = fmaf(p1.z, w1.z, pe1); pe1 = fmaf(p1.w, w1.w, pe1);
        }
        g_pe[pos * S_DIM + c] = pe + pe1;
    } else if (bid == MAXPOS) {
        for (int idx = c; idx < 32 * 64; idx += 256) {
            int p  = idx >> 6;
            int cc = idx & 63;
            float v;
            if (cc < 32) v = pair1_W[cc * 8 + (p >> 2)] + pair1_b[cc];
            else { int c2 = cc - 32; v = pair2_W[c2 * 4 + (p & 3)] + pair2_b[c2]; }
            g_table[idx] = v;
        }
        // transpose seq_W [256][21] -> g_seqWT [21][256]
        for (int idx = c; idx < S_IN * S_DIM; idx += 256) {
            int d  = idx >> 8;          // 0..20
            int ch = idx & 255;         // 0..255
            g_seqWT[idx] = seq_W[ch * S_IN + d];
        }
    } else {
        const int i0 = (bid - MAXPOS - 1) * PROW_PER_BLK;
        for (int r = 0; r < PROW_PER_BLK; r++) {
            int i = i0 + r;
            if (i >= L_TOTAL) break;
            for (int j = c; j < L_TOTAL; j += 256)
                g_prow[i * PROW_PITCH + j] = (unsigned char)pair_id(i, j);
        }
    }
}

// ---------------- fused kernel: one block per (b, i); writes s row + z row ----------
__global__ void __launch_bounds__(256)
fused_kernel(const float* __restrict__ s0, const float* __restrict__ s1,
             const float* __restrict__ s2, const float* __restrict__ s3,
             const float* __restrict__ s4, const float* __restrict__ s5,
             const float* __restrict__ s6,
             const float* __restrict__ seq_b,
             const float* __restrict__ collapse_token,
             const float* __restrict__ collapse_weight,
             const float* __restrict__ region_w,
             float* __restrict__ sout, float* __restrict__ zout)
{
    __shared__ float4 table[32 * 16];
    __shared__ unsigned char prow[PROW_PITCH];
    __shared__ float srow[24];

    const int bl = blockIdx.x;                     // b * L_TOTAL + i
    const int i  = bl % L_TOTAL;
    const int b  = bl / L_TOTAL;
    const int c  = threadIdx.x;

    // Slim prologue: pure copies from L2-resident precomputed tables.
    {
        const float4* gt = (const float4*)g_table;
        table[c]       = gt[c];
        table[c + 256] = gt[c + 256];
        if (c < PROW_PITCH / 4)
            ((unsigned int*)prow)[c] = ((const unsigned int*)(g_prow + i * PROW_PITCH))[c];
    }

    int k = 0, pos = 0;
    if (i > 0) {
        k   = reg_of(i) - 1;
        pos = i - c_starts[k];
        const float* seqp;
        switch (k) {
            case 0: seqp = s0; break;
            case 1: seqp = s1; break;
            case 2: seqp = s2; break;
            case 3: seqp = s3; break;
            case 4: seqp = s4; break;
            case 5: seqp = s5; break;
            default: seqp = s6; break;
        }
        if (c < S_IN)
            srow[c] = seqp[((size_t)b * c_lens[k] + pos) * S_IN + c];
    }
    __syncthreads();

    // ---- s row ----
    float* orow = sout + (size_t)bl * S_DIM;
    if (i == 0) {
        orow[c] = collapse_weight[0] * collapse_token[c];
    } else {
        float se = seq_b[c];
        #pragma unroll
        for (int d = 0; d < S_IN; d++)              // coalesced: [d][c] layout
            se = fmaf(srow[d], g_seqWT[d * S_DIM + c], se);
        float pe = g_pe[pos * S_DIM + c];
        orow[c] = region_w[2 * k] * se + region_w[2 * k + 1] * pe;
    }

    // ---- z row: stream 327*16 float4 streaming stores ----
    float4* zrow = (float4*)zout + (size_t)bl * (L_TOTAL * (Z_DIM / 4));
    const int total = L_TOTAL * (Z_DIM / 4);       // 5232
    #pragma unroll 4
    for (int v = c; v < total; v += 256) {
        int j = v >> 4;
        __stcs(&zrow[v], table[((int)prow[j] << 4) + (v & 15)]);
    }
}

extern "C" void kernel_launch(void* const* d_in, const int* in_sizes, int n_in,
                              void* d_out, int out_size)
{
    (void)in_sizes; (void)n_in; (void)out_size;
    // 0..6 region seqs, 7 seq_W, 8 seq_b, 9 pos_W, 10 pos_b, 11 pair1_W, 12 pair1_b,
    // 13 pair2_W, 14 pair2_b, 15 collapse_token, 16 collapse_weight, 17 region_w,
    // 18..24 masks (unused)
    float* out  = (float*)d_out;
    float* zout = out + (size_t)BB * L_TOTAL * S_DIM;   // z follows s

    setup_kernel<<<MAXPOS + 1 + PROW_BLKS, 256>>>(
        (const float*)d_in[9],  (const float*)d_in[10],
        (const float*)d_in[11], (const float*)d_in[12],
        (const float*)d_in[13], (const float*)d_in[14],
        (const float*)d_in[7]);

    fused_kernel<<<BB * L_TOTAL, 256>>>(
        (const float*)d_in[0], (const float*)d_in[1], (const float*)d_in[2],
        (const float*)d_in[3], (const float*)d_in[4], (const float*)d_in[5],
        (const float*)d_in[6],
        (const float*)d_in[8],
        (const float*)d_in[15], (const float*)d_in[16],
        (const float*)d_in[17],
        out, zout);
}

// round 8
// speedup vs baseline: 1.4502x; 1.0046x over previous
#include <cuda_runtime.h>
#include <cstdint>
#include <math.h>

#define BB 16
#define L_TOTAL 327
#define PROW_PITCH 328
#define S_DIM 256
#define Z_DIM 64
#define S_IN 21
#define PE_DIM 64
#define MAXPOS 104

__constant__ int c_starts[7] = {1, 25, 41, 89, 193, 209, 313};
__constant__ int c_lens[7]   = {24, 16, 48, 104, 16, 104, 14};

// Precomputed scratch
__device__ float g_pe[MAXPOS * S_DIM];                    // PE projection table
__device__ float g_table[32 * 64];                        // z vocabulary
__device__ float g_seqWT[S_IN * S_DIM];                   // seq_W transposed [d][c]
__device__ unsigned char g_prow[L_TOTAL * PROW_PITCH];    // pair-id matrix

__device__ __forceinline__ int reg_of(int i) {
    if (i == 0)  return 0;
    if (i < 25)  return 1;
    if (i < 41)  return 2;
    if (i < 89)  return 3;
    if (i < 193) return 4;
    if (i < 209) return 5;
    if (i < 313) return 6;
    return 7;
}

__device__ __forceinline__ int pair_id(int i, int j) {
    int ri = reg_of(i), rj = reg_of(j);
    int p = 0;
    if (i == 0 || j == 0) p = 1;
    if (i == 0 && j == 0) p = 0;
    bool cb = (ri == 1) && (rj == 1);
    int d = (i > j) ? (i - j) : (j - i);
    if (cb && d == 1) p = 2;
    if (cb && i != j && d != 1) p = 3;
    if ((ri == 1 && rj >= 2) || (ri >= 2 && rj == 1)) p = 4;
    if (ri >= 2 && ri == rj) p = 5 + (ri - 2);
    if (ri >= 2 && rj >= 2 && ri != rj) {
        int a = (ri < rj ? ri : rj) - 2;
        int b = (ri > rj ? ri : rj) - 2;
        p = 11 + a * (11 - a) / 2 + (b - a - 1);
    }
    return (p < 31) ? p : 31;
}

// ---------------- setup kernel ----------------
// blocks [0,104):            g_pe rows
// block  104:                g_table + seq_W transpose
// blocks [105, 105+327):     g_prow, 1 row each (short critical path)
__global__ void __launch_bounds__(256)
setup_kernel(const float* __restrict__ pos_W, const float* __restrict__ pos_b,
             const float* __restrict__ pair1_W, const float* __restrict__ pair1_b,
             const float* __restrict__ pair2_W, const float* __restrict__ pair2_b,
             const float* __restrict__ seq_W)
{
    const int bid = blockIdx.x;
    const int c   = threadIdx.x;

    if (bid < MAXPOS) {
        __shared__ float4 perow4[PE_DIM / 4];
        const int pos = bid;
        if (c < PE_DIM) {
            float inv = exp2f(-(float)c * (13.287712379549449f / 64.0f));
            float ang = (float)pos * inv;
            ((float*)perow4)[c] = (c & 1) ? cosf(ang) : sinf(ang);
        }
        __syncthreads();
        float pe = pos_b[c];
        const float4* pw = (const float4*)(pos_W + c * PE_DIM);
        float pe1 = 0.f;
        #pragma unroll
        for (int q = 0; q < 16; q += 2) {
            float4 w0 = pw[q],   p0 = perow4[q];
            float4 w1 = pw[q+1], p1 = perow4[q+1];
            pe  = fmaf(p0.x, w0.x, pe);  pe  = fmaf(p0.y, w0.y, pe);
            pe  = fmaf(p0.z, w0.z, pe);  pe  = fmaf(p0.w, w0.w, pe);
            pe1 = fmaf(p1.x, w1.x, pe1); pe1 = fmaf(p1.y, w1.y, pe1);
            pe1 = fmaf(p1.z, w1.z, pe1); pe1 = fmaf(p1.w, w1.w, pe1);
        }
        g_pe[pos * S_DIM + c] = pe + pe1;
    } else if (bid == MAXPOS) {
        for (int idx = c; idx < 32 * 64; idx += 256) {
            int p  = idx >> 6;
            int cc = idx & 63;
            float v;
            if (cc < 32) v = pair1_W[cc * 8 + (p >> 2)] + pair1_b[cc];
            else { int c2 = cc - 32; v = pair2_W[c2 * 4 + (p & 3)] + pair2_b[c2]; }
            g_table[idx] = v;
        }
        // transpose seq_W [256][21] -> g_seqWT [21][256]
        for (int idx = c; idx < S_IN * S_DIM; idx += 256) {
            int d  = idx >> 8;
            int ch = idx & 255;
            g_seqWT[idx] = seq_W[ch * S_IN + d];
        }
    } else {
        const int i = bid - MAXPOS - 1;            // 0..326
        for (int j = c; j < L_TOTAL; j += 256)
            g_prow[i * PROW_PITCH + j] = (unsigned char)pair_id(i, j);
    }
}

// ---------------- fused kernel (PDL secondary): one block per (b, i) ----------------
__global__ void __launch_bounds__(256)
fused_kernel(const float* __restrict__ s0, const float* __restrict__ s1,
             const float* __restrict__ s2, const float* __restrict__ s3,
             const float* __restrict__ s4, const float* __restrict__ s5,
             const float* __restrict__ s6,
             const float* __restrict__ seq_b,
             const float* __restrict__ collapse_token,
             const float* __restrict__ collapse_weight,
             const float* __restrict__ region_w,
             float* __restrict__ sout, float* __restrict__ zout)
{
    __shared__ float4 table[32 * 16];
    __shared__ unsigned char prow[PROW_PITCH];
    __shared__ float srow[24];

    const int bl = blockIdx.x;                     // b * L_TOTAL + i
    const int i  = bl % L_TOTAL;
    const int b  = bl / L_TOTAL;
    const int c  = threadIdx.x;

    // --- pre-sync work: only touches harness inputs, not setup outputs ---
    int k = 0, pos = 0;
    const float* seqp = s0;
    if (i > 0) {
        k   = reg_of(i) - 1;
        pos = i - c_starts[k];
        switch (k) {
            case 0: seqp = s0; break;
            case 1: seqp = s1; break;
            case 2: seqp = s2; break;
            case 3: seqp = s3; break;
            case 4: seqp = s4; break;
            case 5: seqp = s5; break;
            default: seqp = s6; break;
        }
        if (c < S_IN)
            srow[c] = seqp[((size_t)b * c_lens[k] + pos) * S_IN + c];
    }

#if __CUDA_ARCH__ >= 900
    cudaGridDependencySynchronize();               // wait for setup_kernel results
#endif

    // --- post-sync: copy precomputed tables from L2 ---
    {
        const float4* gt = (const float4*)g_table;
        table[c]       = gt[c];
        table[c + 256] = gt[c + 256];
        if (c < PROW_PITCH / 4)
            ((unsigned int*)prow)[c] = ((const unsigned int*)(g_prow + i * PROW_PITCH))[c];
    }
    __syncthreads();

    // ---- s row ----
    float* orow = sout + (size_t)bl * S_DIM;
    if (i == 0) {
        orow[c] = collapse_weight[0] * collapse_token[c];
    } else {
        float se = seq_b[c];
        #pragma unroll
        for (int d = 0; d < S_IN; d++)              // coalesced: [d][c] layout
            se = fmaf(srow[d], g_seqWT[d * S_DIM + c], se);
        float pe = g_pe[pos * S_DIM + c];
        orow[c] = region_w[2 * k] * se + region_w[2 * k + 1] * pe;
    }

    // ---- z row: stream 327*16 float4 streaming stores ----
    float4* zrow = (float4*)zout + (size_t)bl * (L_TOTAL * (Z_DIM / 4));
    const int total = L_TOTAL * (Z_DIM / 4);       // 5232
    #pragma unroll 4
    for (int v = c; v < total; v += 256) {
        int j = v >> 4;
        __stcs(&zrow[v], table[((int)prow[j] << 4) + (v & 15)]);
    }
}

extern "C" void kernel_launch(void* const* d_in, const int* in_sizes, int n_in,
                              void* d_out, int out_size)
{
    (void)in_sizes; (void)n_in; (void)out_size;
    // 0..6 region seqs, 7 seq_W, 8 seq_b, 9 pos_W, 10 pos_b, 11 pair1_W, 12 pair1_b,
    // 13 pair2_W, 14 pair2_b, 15 collapse_token, 16 collapse_weight, 17 region_w,
    // 18..24 masks (unused)
    float* out  = (float*)d_out;
    float* zout = out + (size_t)BB * L_TOTAL * S_DIM;   // z follows s

    setup_kernel<<<MAXPOS + 1 + L_TOTAL, 256>>>(
        (const float*)d_in[9],  (const float*)d_in[10],
        (const float*)d_in[11], (const float*)d_in[12],
        (const float*)d_in[13], (const float*)d_in[14],
        (const float*)d_in[7]);

    // PDL launch: fused overlaps setup's tail; device-side sync gates table reads.
    {
        cudaLaunchConfig_t cfg = {};
        cfg.gridDim  = dim3(BB * L_TOTAL);
        cfg.blockDim = dim3(256);
        cfg.dynamicSmemBytes = 0;
        cudaLaunchAttribute attr[1];
        attr[0].id = cudaLaunchAttributeProgrammaticStreamSerialization;
        attr[0].val.programmaticStreamSerializationAllowed = 1;
        cfg.attrs = attr;
        cfg.numAttrs = 1;

        const float* a0  = (const float*)d_in[0];
        const float* a1  = (const float*)d_in[1];
        const float* a2  = (const float*)d_in[2];
        const float* a3  = (const float*)d_in[3];
        const float* a4  = (const float*)d_in[4];
        const float* a5  = (const float*)d_in[5];
        const float* a6  = (const float*)d_in[6];
        const float* sb  = (const float*)d_in[8];
        const float* ct  = (const float*)d_in[15];
        const float* cw  = (const float*)d_in[16];
        const float* rw  = (const float*)d_in[17];

        cudaLaunchKernelEx(&cfg, fused_kernel,
                           a0, a1, a2, a3, a4, a5, a6,
                           sb, ct, cw, rw, out, zout);
    }
}